// round 4
// baseline (speedup 1.0000x reference)
#include <cuda_runtime.h>
#include <cstdint>

// 12-bit ripple-carry adder over {0,1}-valued float32 arrays.
// A,B: [BATCH, 12] float32, col 11 = LSB (weight 2^(11-i)).
// Out: sums [BATCH,12] at d_out[0..B*12), carry [BATCH] at d_out[B*12..B*13).
//
// Streaming-roofline version:
//  - thread t handles 4 contiguous float4 chunks (8 front-batched LDG.128, MLP 8)
//  - __ldcs/__stcs evict-first (620MB stream, zero reuse)
//  - 6KB smem nibble exchange assembles 12-bit rows; block = 384 thr = 512 rows

__device__ __forceinline__ unsigned f2b(float x) {
    return __float_as_uint(x) != 0u ? 1u : 0u;   // x is exactly 0.0f or 1.0f
}

__device__ __forceinline__ unsigned pack_nib(float4 a, float4 b) {
    unsigned na = (f2b(a.x) << 3) | (f2b(a.y) << 2) | (f2b(a.z) << 1) | f2b(a.w);
    unsigned nb = (f2b(b.x) << 3) | (f2b(b.y) << 2) | (f2b(b.z) << 1) | f2b(b.w);
    return na | (nb << 4);
}

__device__ __forceinline__ unsigned row_sum(const unsigned* nib, int rb) {
    unsigned c0 = nib[rb + 0], c1 = nib[rb + 1], c2 = nib[rb + 2];
    // chunk j holds bit-weights: j=0 -> bits 11..8, j=1 -> 7..4, j=2 -> 3..0
    unsigned av = ((c0 & 0xFu) << 8) | ((c1 & 0xFu) << 4) | (c2 & 0xFu);
    unsigned bv = ((c0 >> 4) << 8)  | (((c1 >> 4) & 0xFu) << 4) | ((c2 >> 4) & 0xFu);
    return av + bv;   // 13-bit result
}

__device__ __forceinline__ float4 nib_to_f4(unsigned on) {
    float4 o;
    o.x = (on & 8u) ? 1.0f : 0.0f;
    o.y = (on & 4u) ? 1.0f : 0.0f;
    o.z = (on & 2u) ? 1.0f : 0.0f;
    o.w = (on & 1u) ? 1.0f : 0.0f;
    return o;
}

#define TPB 384
#define CPT 4                     // chunks per thread
#define CHUNKS_PER_BLOCK (TPB * CPT)   // 1536
#define ROWS_PER_BLOCK (CHUNKS_PER_BLOCK / 3)  // 512

__global__ void __launch_bounds__(TPB) adder12_kernel(
    const float4* __restrict__ A4,
    const float4* __restrict__ B4,
    float4* __restrict__ S4,      // sums, float4[batch*3]
    float* __restrict__ carry,    // [batch]
    int nchunks,                  // batch*3
    int batch)
{
    __shared__ unsigned nib[CHUNKS_PER_BLOCK];

    const int tid = threadIdx.x;
    const int base = blockIdx.x * CHUNKS_PER_BLOCK + tid;

    // Front-batched streaming loads (MLP 8)
    float4 a[CPT], b[CPT];
    bool v[CPT];
#pragma unroll
    for (int k = 0; k < CPT; k++) {
        int ci = base + k * TPB;
        v[k] = (ci < nchunks);
        if (v[k]) { a[k] = __ldcs(&A4[ci]); b[k] = __ldcs(&B4[ci]); }
    }

#pragma unroll
    for (int k = 0; k < CPT; k++)
        nib[tid + k * TPB] = v[k] ? pack_nib(a[k], b[k]) : 0u;
    __syncthreads();

    // Output chunks
#pragma unroll
    for (int k = 0; k < CPT; k++) {
        int li = tid + k * TPB;              // local chunk index
        int lrow = li / 3;
        int part = li - lrow * 3;
        unsigned s = row_sum(nib, lrow * 3);
        unsigned on = (s >> (8 - 4 * part)) & 0xFu;
        if (v[k]) __stcs(&S4[base + k * TPB], nib_to_f4(on));
    }

    // Carry-out: 512 rows per block, threads cover them in coalesced strides.
#pragma unroll
    for (int r = tid; r < ROWS_PER_BLOCK; r += TPB) {
        int row = blockIdx.x * ROWS_PER_BLOCK + r;
        if (row < batch) {
            unsigned s = row_sum(nib, r * 3);
            __stcs(&carry[row], (s >> 12) ? 1.0f : 0.0f);
        }
    }
}

extern "C" void kernel_launch(void* const* d_in, const int* in_sizes, int n_in,
                              void* d_out, int out_size) {
    const float* A = (const float*)d_in[0];
    const float* B = (const float*)d_in[1];
    float* out = (float*)d_out;

    int batch = in_sizes[0] / 12;
    int nchunks = batch * 3;

    float* sums = out;
    float* carry = out + (long)batch * 12;

    int blocks = (batch + ROWS_PER_BLOCK - 1) / ROWS_PER_BLOCK;
    adder12_kernel<<<blocks, TPB>>>(
        (const float4*)A, (const float4*)B, (float4*)sums, carry, nchunks, batch);
}

// round 5
// speedup vs baseline: 1.0511x; 1.0511x over previous
#include <cuda_runtime.h>
#include <cstdint>

// 12-bit ripple-carry adder over {0,1}-valued float32 arrays.
// A,B: [BATCH, 12] float32, col 11 = LSB (weight 2^(11-i)).
// Out: sums [BATCH,12] at d_out[0..B*12), carry [BATCH] at d_out[B*12..B*13).
//
// R3 config (CPT=2, TPB=384: best measured 84.7us kernel) with a
// predicate-free fast path: BATCH divides evenly into blocks, so the common
// case launches a kernel with zero bounds checks (fewer regs, higher occ).

__device__ __forceinline__ unsigned f2b(float x) {
    return __float_as_uint(x) != 0u ? 1u : 0u;   // x is exactly 0.0f or 1.0f
}

__device__ __forceinline__ unsigned pack_nib(float4 a, float4 b) {
    unsigned na = (f2b(a.x) << 3) | (f2b(a.y) << 2) | (f2b(a.z) << 1) | f2b(a.w);
    unsigned nb = (f2b(b.x) << 3) | (f2b(b.y) << 2) | (f2b(b.z) << 1) | f2b(b.w);
    return na | (nb << 4);
}

__device__ __forceinline__ unsigned row_sum(const unsigned* nib, int rb) {
    unsigned c0 = nib[rb + 0], c1 = nib[rb + 1], c2 = nib[rb + 2];
    // chunk j holds bit-weights: j=0 -> bits 11..8, j=1 -> 7..4, j=2 -> 3..0
    unsigned av = ((c0 & 0xFu) << 8) | ((c1 & 0xFu) << 4) | (c2 & 0xFu);
    unsigned bv = ((c0 >> 4) << 8)  | (((c1 >> 4) & 0xFu) << 4) | ((c2 >> 4) & 0xFu);
    return av + bv;   // 13-bit result
}

__device__ __forceinline__ float4 nib_to_f4(unsigned on) {
    float4 o;
    o.x = (on & 8u) ? 1.0f : 0.0f;
    o.y = (on & 4u) ? 1.0f : 0.0f;
    o.z = (on & 2u) ? 1.0f : 0.0f;
    o.w = (on & 1u) ? 1.0f : 0.0f;
    return o;
}

#define TPB 384
#define CHUNKS_PER_BLOCK (TPB * 2)             // 768
#define ROWS_PER_BLOCK (CHUNKS_PER_BLOCK / 3)  // 256

// ---- Fast path: nchunks % CHUNKS_PER_BLOCK == 0, no bounds checks ----
__global__ void __launch_bounds__(TPB) adder12_exact(
    const float4* __restrict__ A4,
    const float4* __restrict__ B4,
    float4* __restrict__ S4,
    float* __restrict__ carry)
{
    __shared__ unsigned nib[CHUNKS_PER_BLOCK];

    const int tid = threadIdx.x;
    const int c0i = blockIdx.x * CHUNKS_PER_BLOCK + tid;
    const int c1i = c0i + TPB;

    // Front-batched streaming loads (MLP 4)
    float4 a0 = __ldcs(&A4[c0i]);
    float4 b0 = __ldcs(&B4[c0i]);
    float4 a1 = __ldcs(&A4[c1i]);
    float4 b1 = __ldcs(&B4[c1i]);

    nib[tid]       = pack_nib(a0, b0);
    nib[tid + TPB] = pack_nib(a1, b1);
    __syncthreads();

    {
        int lrow = tid / 3;
        int part = tid - lrow * 3;
        unsigned s = row_sum(nib, lrow * 3);
        __stcs(&S4[c0i], nib_to_f4((s >> (8 - 4 * part)) & 0xFu));
    }
    {
        int li = tid + TPB;
        int lrow = li / 3;
        int part = li - lrow * 3;
        unsigned s = row_sum(nib, lrow * 3);
        __stcs(&S4[c1i], nib_to_f4((s >> (8 - 4 * part)) & 0xFu));
    }

    if (tid < ROWS_PER_BLOCK) {
        unsigned s = row_sum(nib, tid * 3);
        __stcs(&carry[blockIdx.x * ROWS_PER_BLOCK + tid],
               (s >> 12) ? 1.0f : 0.0f);
    }
}

// ---- Guarded fallback for non-divisible sizes ----
__global__ void __launch_bounds__(TPB) adder12_guarded(
    const float4* __restrict__ A4,
    const float4* __restrict__ B4,
    float4* __restrict__ S4,
    float* __restrict__ carry,
    int nchunks, int batch)
{
    __shared__ unsigned nib[CHUNKS_PER_BLOCK];

    const int tid = threadIdx.x;
    const int c0i = blockIdx.x * CHUNKS_PER_BLOCK + tid;
    const int c1i = c0i + TPB;
    const bool v0 = (c0i < nchunks);
    const bool v1 = (c1i < nchunks);

    float4 a0, b0, a1, b1;
    if (v0) { a0 = __ldcs(&A4[c0i]); b0 = __ldcs(&B4[c0i]); }
    if (v1) { a1 = __ldcs(&A4[c1i]); b1 = __ldcs(&B4[c1i]); }

    nib[tid]       = v0 ? pack_nib(a0, b0) : 0u;
    nib[tid + TPB] = v1 ? pack_nib(a1, b1) : 0u;
    __syncthreads();

    {
        int lrow = tid / 3;
        int part = tid - lrow * 3;
        unsigned s = row_sum(nib, lrow * 3);
        if (v0) __stcs(&S4[c0i], nib_to_f4((s >> (8 - 4 * part)) & 0xFu));
    }
    {
        int li = tid + TPB;
        int lrow = li / 3;
        int part = li - lrow * 3;
        unsigned s = row_sum(nib, lrow * 3);
        if (v1) __stcs(&S4[c1i], nib_to_f4((s >> (8 - 4 * part)) & 0xFu));
    }

    if (tid < ROWS_PER_BLOCK) {
        int row = blockIdx.x * ROWS_PER_BLOCK + tid;
        if (row < batch) {
            unsigned s = row_sum(nib, tid * 3);
            __stcs(&carry[row], (s >> 12) ? 1.0f : 0.0f);
        }
    }
}

extern "C" void kernel_launch(void* const* d_in, const int* in_sizes, int n_in,
                              void* d_out, int out_size) {
    const float* A = (const float*)d_in[0];
    const float* B = (const float*)d_in[1];
    float* out = (float*)d_out;

    int batch = in_sizes[0] / 12;
    int nchunks = batch * 3;

    float* sums = out;
    float* carry = out + (long)batch * 12;

    if (nchunks % CHUNKS_PER_BLOCK == 0) {
        int blocks = nchunks / CHUNKS_PER_BLOCK;
        adder12_exact<<<blocks, TPB>>>(
            (const float4*)A, (const float4*)B, (float4*)sums, carry);
    } else {
        int blocks = (nchunks + CHUNKS_PER_BLOCK - 1) / CHUNKS_PER_BLOCK;
        adder12_guarded<<<blocks, TPB>>>(
            (const float4*)A, (const float4*)B, (float4*)sums, carry,
            nchunks, batch);
    }
}